// round 14
// baseline (speedup 1.0000x reference)
#include <cuda_runtime.h>
#include <cuda_bf16.h>
#include <cstdint>

#define GRID_W 112
#define HW (GRID_W*GRID_W)
#define NV 512
#define NP 128
#define M (NP*NV)        /* 65536 rows */
#define S 128
#define GRID_C 128       /* persistent CTAs */
#define TILES_PER_CTA 4

// ---------------------------------------------------------------------------
// PTX helpers (sm_80+ : valid for compute_103)
// ---------------------------------------------------------------------------
__device__ __forceinline__ uint32_t smem_u32(const void* p) {
    uint32_t a;
    asm("{ .reg .u64 t; cvta.to.shared.u64 t, %1; cvt.u32.u64 %0, t; }" : "=r"(a) : "l"(p));
    return a;
}
__device__ __forceinline__ void ldmx4(uint32_t* r, uint32_t addr) {
    asm volatile("ldmatrix.sync.aligned.m8n8.x4.shared.b16 {%0,%1,%2,%3}, [%4];"
        : "=r"(r[0]), "=r"(r[1]), "=r"(r[2]), "=r"(r[3]) : "r"(addr));
}
__device__ __forceinline__ void mma16816(float* d, const uint32_t* a,
                                         uint32_t b0, uint32_t b1) {
    asm volatile(
        "mma.sync.aligned.m16n8k16.row.col.f32.bf16.bf16.f32 "
        "{%0,%1,%2,%3}, {%4,%5,%6,%7}, {%8,%9}, {%0,%1,%2,%3};"
        : "+f"(d[0]), "+f"(d[1]), "+f"(d[2]), "+f"(d[3])
        : "r"(a[0]), "r"(a[1]), "r"(a[2]), "r"(a[3]), "r"(b0), "r"(b1));
}
#define CP_ASYNC16(dst, src) \
    asm volatile("cp.async.cg.shared.global [%0], [%1], 16;" :: "r"(dst), "l"(src))
#define CP_COMMIT() asm volatile("cp.async.commit_group;")
#define CP_WAIT0()  asm volatile("cp.async.wait_group 0;")

// 4-tap ring average on 4 bf16 lanes (one uint2) : 0.25*(a+b+c+d)
__device__ __forceinline__ uint2 ring4_bf16x4(uint2 a, uint2 b, uint2 c, uint2 d) {
    const __nv_bfloat162 q = __float2bfloat162_rn(0.25f);
    __nv_bfloat162 s0 = __hmul2(q, __hadd2(__hadd2(*(__nv_bfloat162*)&a.x, *(__nv_bfloat162*)&b.x),
                                           __hadd2(*(__nv_bfloat162*)&c.x, *(__nv_bfloat162*)&d.x)));
    __nv_bfloat162 s1 = __hmul2(q, __hadd2(__hadd2(*(__nv_bfloat162*)&a.y, *(__nv_bfloat162*)&b.y),
                                           __hadd2(*(__nv_bfloat162*)&c.y, *(__nv_bfloat162*)&d.y)));
    return make_uint2(*(uint32_t*)&s0, *(uint32_t*)&s1);
}

// ---------------------------------------------------------------------------
// Gather: one unit = (row, 4-channel chunk j) of the sampled feature tile
// ---------------------------------------------------------------------------
struct GTaps { float4 m00, m01, m10, m11; float wx, wy; };

__device__ __forceinline__ void gt_load(const float* __restrict__ feature,
                                        const float* __restrict__ poly,
                                        int grow, int j, int step, GTaps& T)
{
    int p = grow >> 9;
    float px = poly[grow*2], py = poly[grow*2+1];
    const float4* fb = (const float4*)(feature + (size_t)p * HW * 64);
    if (step == 0) {
        int xi = (int)fminf(fmaxf(floorf(px*GRID_W), 0.f), 111.f);
        int yi = (int)fminf(fmaxf(floorf(py*GRID_W), 0.f), 111.f);
        T.m00 = fb[(size_t)(xi + yi*GRID_W)*16 + j];
        T.wx = 0.f; T.wy = 0.f;
    } else {
        float Xs = px*GRID_W, Ys = py*GRID_W;
        float X0 = floorf(Xs), Y0 = floorf(Ys);
        T.wx = Xs - X0; T.wy = Ys - Y0;
        int x0 = (int)fminf(fmaxf(X0,     0.f), 111.f);
        int x1 = (int)fminf(fmaxf(X0+1.f, 0.f), 111.f);
        int y0 = (int)fminf(fmaxf(Y0,     0.f), 111.f);
        int y1 = (int)fminf(fmaxf(Y0+1.f, 0.f), 111.f);
        T.m00 = fb[(size_t)(x0 + y0*GRID_W)*16 + j];
        T.m01 = fb[(size_t)(x0 + y1*GRID_W)*16 + j];
        T.m10 = fb[(size_t)(x1 + y0*GRID_W)*16 + j];
        T.m11 = fb[(size_t)(x1 + y1*GRID_W)*16 + j];
    }
}

__device__ __forceinline__ uint2 gt_consume(const GTaps& T, int step)
{
    float4 v;
    if (step == 0) {
        v = T.m00;
    } else {
        float w00 = (1.f-T.wx)*(1.f-T.wy), w01 = (1.f-T.wx)*T.wy;
        float w10 = T.wx*(1.f-T.wy),       w11 = T.wx*T.wy;
        v.x = w00*T.m00.x + w01*T.m01.x + w10*T.m10.x + w11*T.m11.x;
        v.y = w00*T.m00.y + w01*T.m01.y + w10*T.m10.y + w11*T.m11.y;
        v.z = w00*T.m00.z + w01*T.m01.z + w10*T.m10.z + w11*T.m11.z;
        v.w = w00*T.m00.w + w01*T.m01.w + w10*T.m10.w + w11*T.m11.w;
    }
    __nv_bfloat162 o0 = __float22bfloat162_rn(make_float2(v.x, v.y));
    __nv_bfloat162 o1 = __float22bfloat162_rn(make_float2(v.z, v.w));
    return make_uint2(*(uint32_t*)&o0, *(uint32_t*)&o1);
}

// ---------------------------------------------------------------------------
// Scratch globals
// ---------------------------------------------------------------------------
__device__ float g_polyA[(size_t)M*2];
__device__ float g_polyB[(size_t)M*2];
__device__ __align__(16) __nv_bfloat16 g_w1T[3*128*128];   // [step][n][k] k<64:W1s, k>=64:W1n
__device__ __align__(16) __nv_bfloat16 g_w2sT[3*128*128];
__device__ __align__(16) __nv_bfloat16 g_w2nT[3*128*128];
__device__ float g_pw[3*4*128];  // poly-weight rows: Ws[64],Ws[65],Wn[64],Wn[65]

// ---------------------------------------------------------------------------
// Prep: transpose + bf16-convert weights. grid (3 steps x 8 slices)
// ---------------------------------------------------------------------------
__global__ void prep_kernel(const float* __restrict__ W1s, const float* __restrict__ W1n,
                            const float* __restrict__ W2s, const float* __restrict__ W2n)
{
    int i = blockIdx.x;
    int slice = blockIdx.y;
    int tid = threadIdx.x + slice*256;          // 0..2047 across slices
    const float* w1s = W1s + (size_t)i*66*128;
    const float* w1n = W1n + (size_t)i*66*128;
    for (int idx = tid; idx < 128*128; idx += 2048) {
        int n = idx >> 7, k = idx & 127;
        float v = (k < 64) ? w1s[k*128 + n] : w1n[(k-64)*128 + n];
        g_w1T[(size_t)i*16384 + idx] = __float2bfloat16(v);
    }
    if (slice == 0 && threadIdx.x < 128) {
        int t = threadIdx.x;
        g_pw[i*512 +       t] = w1s[64*128 + t];
        g_pw[i*512 + 128 + t] = w1s[65*128 + t];
        g_pw[i*512 + 256 + t] = w1n[64*128 + t];
        g_pw[i*512 + 384 + t] = w1n[65*128 + t];
    }
    const float* w2s = W2s + (size_t)i*128*128;
    const float* w2n = W2n + (size_t)i*128*128;
    for (int idx = tid; idx < 128*128; idx += 2048) {
        int n = idx >> 7, k = idx & 127;
        g_w2sT[(size_t)i*16384 + idx] = __float2bfloat16(w2s[k*128 + n]);
        g_w2nT[(size_t)i*16384 + idx] = __float2bfloat16(w2n[k*128 + n]);
    }
}

// ---------------------------------------------------------------------------
// Persistent fused kernel: in-kernel prefetched gather + GEMM1 + stencil +
// GEMM2 + FC + poly update. 128 CTAs x 4 tiles, 512 thr, 16 warps (4m x 4n).
// ---------------------------------------------------------------------------
#define LDW 272
#define LDX 144
#define SM_W1    0
#define SM_W2S   34816
#define SM_W2N   69632
#define SM_HS    104448
#define SM_HN    140352
#define SM_XN    175168
#define SM_XR    195904
#define SM_PW    217216
#define SM_B1    219264
#define SM_B2    219776
#define SM_FC    220288
#define SM_PP    221312   /* 136*2 f32 */
#define SM_RED   222400   /* 128*8 f32 */
#define SM_TOTAL 226496

// gather a whole tile's XR rows (0..135 = poly rows -4..131), 2176 units
__device__ __forceinline__ void gather_tile(const float* __restrict__ feature,
                                            const float* __restrict__ poly,
                                            char* sm, int pbase, int n0,
                                            int step, int tid)
{
    #pragma unroll
    for (int base = 0; base < 2048; base += 1024) {
        int wA = base + tid, wB = base + 512 + tid;
        int rA = wA >> 4, jA = wA & 15;
        int rB = wB >> 4, jB = wB & 15;
        int gA = pbase + ((n0 + rA - 4 + NV) & (NV-1));
        int gB = pbase + ((n0 + rB - 4 + NV) & (NV-1));
        GTaps A, B;
        gt_load(feature, poly, gA, jA, step, A);
        gt_load(feature, poly, gB, jB, step, B);
        uint2 oA = gt_consume(A, step);
        uint2 oB = gt_consume(B, step);
        *(uint2*)(sm + SM_XR + rA*LDX + jA*8) = oA;
        *(uint2*)(sm + SM_XR + rB*LDX + jB*8) = oB;
    }
    if (tid < 128) {
        int w = 2048 + tid;
        int r = w >> 4, j = w & 15;
        int g = pbase + ((n0 + r - 4 + NV) & (NV-1));
        GTaps A;
        gt_load(feature, poly, g, j, step, A);
        uint2 o = gt_consume(A, step);
        *(uint2*)(sm + SM_XR + r*LDX + j*8) = o;
    }
}

__global__ void __launch_bounds__(512, 1)
gemm12_kernel(const float* __restrict__ feature,
              const float* __restrict__ poly_in,
              float* __restrict__ poly_out,
              const float* __restrict__ b1_g,
              const float* __restrict__ b2_g,
              const float* __restrict__ wfc_g,
              const float* __restrict__ bfc_g,
              int step)
{
    extern __shared__ char sm[];
    uint32_t sb = smem_u32(sm);
    int tid = threadIdx.x, wid = tid >> 5, lane = tid & 31;
    int wm = wid & 3, wn = wid >> 2;
    int l7 = lane & 7, l8 = (lane >> 3) & 1, l16 = (lane >> 4) & 1;

    // ------- prologue: cp.async weights; scalars; XR zero-pad; tile0 gather --
    {
        const char* w1p  = (const char*)(g_w1T  + (size_t)step*16384);
        const char* w2sp = (const char*)(g_w2sT + (size_t)step*16384);
        const char* w2np = (const char*)(g_w2nT + (size_t)step*16384);
        for (int idx = tid; idx < 128*16; idx += 512) {
            int r = idx >> 4, q = idx & 15;
            CP_ASYNC16(sb + SM_W1  + r*LDW + q*16, w1p  + idx*16);
            CP_ASYNC16(sb + SM_W2S + r*LDW + q*16, w2sp + idx*16);
            CP_ASYNC16(sb + SM_W2N + r*LDW + q*16, w2np + idx*16);
        }
        CP_COMMIT();
        if (tid < 128) {
            ((float*)(sm + SM_B1))[tid] = b1_g[tid];
            ((float*)(sm + SM_B2))[tid] = b2_g[tid];
        }
        if (tid < 256) ((float*)(sm + SM_FC))[tid] = wfc_g[tid];
        ((float*)(sm + SM_PW))[tid] = g_pw[step*512 + tid];
        if (tid < 432) {                      // zero XR rows 136..147 (one-time)
            int r = 136 + tid/36, w = tid%36;
            *(uint32_t*)(sm + SM_XR + r*LDX + w*4) = 0;
        }
        // gather tile 0 directly into XR (overlaps weight cp.async)
        int r0 = blockIdx.x * 128;
        int n0 = r0 & (NV-1);
        gather_tile(feature, poly_in, sm, r0 - n0, n0, step, tid);
    }

    for (int t = 0; t < TILES_PER_CTA; t++) {
        int r0 = (t*GRID_C + blockIdx.x) * 128;
        int n0 = r0 & (NV-1);
        int pbase = r0 - n0;

        CP_WAIT0();
        __syncthreads();   // XR(t)+weights ready; prior tile fully done

        // poly rows -4..131 for this tile
        if (tid < 272) {
            int rr = tid >> 1, c = tid & 1;
            int g = pbase + ((n0 + rr - 4 + NV) & (NV-1));
            ((float*)(sm + SM_PP))[tid] = poly_in[(size_t)g*2 + c];
        }

        // ---- XN ring stencil (rows 0..143), bf16x2 SIMD, uint2 grain ----
        for (int w = tid; w < 144*16; w += 512) {
            int r = w >> 4, j = w & 15;
            uint2 a = *(uint2*)(sm + SM_XR + (r  )*LDX + j*8);
            uint2 b = *(uint2*)(sm + SM_XR + (r+1)*LDX + j*8);
            uint2 c = *(uint2*)(sm + SM_XR + (r+3)*LDX + j*8);
            uint2 d = *(uint2*)(sm + SM_XR + (r+4)*LDX + j*8);
            *(uint2*)(sm + SM_XN + r*LDX + j*8) = ring4_bf16x4(a, b, c, d);
        }
        __syncthreads();   // XN ready (XR stays live through MMA1)

        // ---- MMA1: K=128 (kt<4 self from XR; kt>=4 ring from XN) ----
        //      Halo (rows 128..143): every warp computes one n8 sub-block.
        float acc1[2][4][4];
        float accH[4];
        #pragma unroll
        for (int mf = 0; mf < 2; mf++)
            #pragma unroll
            for (int nf = 0; nf < 4; nf++)
                #pragma unroll
                for (int j = 0; j < 4; j++) acc1[mf][nf][j] = 0.f;
        #pragma unroll
        for (int j = 0; j < 4; j++) accH[j] = 0.f;

        int halo_nf2 = wm >> 1;
        int halo_hi  = wm & 1;

        #pragma unroll
        for (int kt = 0; kt < 8; kt++) {
            uint32_t a[2][4], ah[4];
            #pragma unroll
            for (int mf = 0; mf < 2; mf++) {
                uint32_t arow = wm*32 + mf*16 + l7 + l8*8;
                uint32_t addr = (kt < 4)
                    ? sb + SM_XR + (2 + arow)*LDX + l16*16 + kt*32
                    : sb + SM_XN + arow*LDX + l16*16 + (kt-4)*32;
                ldmx4(a[mf], addr);
            }
            {
                uint32_t hrow = 128 + l7 + l8*8;
                uint32_t addr = (kt < 4)
                    ? sb + SM_XR + (2 + hrow)*LDX + l16*16 + kt*32
                    : sb + SM_XN + hrow*LDX + l16*16 + (kt-4)*32;
                ldmx4(ah, addr);
            }
            #pragma unroll
            for (int nf2 = 0; nf2 < 2; nf2++) {
                uint32_t b[4];
                ldmx4(b, sb + SM_W1 + (wn*32 + nf2*16 + l16*8 + l7)*LDW + kt*32 + l8*16);
                #pragma unroll
                for (int mf = 0; mf < 2; mf++) {
                    mma16816(acc1[mf][2*nf2],   a[mf], b[0], b[1]);
                    mma16816(acc1[mf][2*nf2+1], a[mf], b[2], b[3]);
                }
                if (nf2 == halo_nf2) {
                    if (halo_hi) mma16816(accH, ah, b[2], b[3]);
                    else         mma16816(accH, ah, b[0], b[1]);
                }
            }
        }

        // ---- epilogue1 -> Hs (HS private; no pre-sync needed) ----
        {
            const float* PP = (const float*)(sm + SM_PP);
            const float* B  = (const float*)(sm + SM_B1);
            const float* PW = (const float*)(sm + SM_PW);
            int rlo = lane >> 2, qc = (lane & 3)*2;
            #pragma unroll
            for (int mf = 0; mf < 2; mf++) {
                int hr = wm*32 + mf*16 + rlo;
                float px0 = PP[(hr+2)*2],  py0 = PP[(hr+2)*2+1];
                float ax0 = 0.25f*(PP[hr*2]   + PP[(hr+1)*2]   + PP[(hr+3)*2]   + PP[(hr+4)*2]);
                float ay0 = 0.25f*(PP[hr*2+1] + PP[(hr+1)*2+1] + PP[(hr+3)*2+1] + PP[(hr+4)*2+1]);
                int r1 = hr + 8;
                float px1 = PP[(r1+2)*2],  py1 = PP[(r1+2)*2+1];
                float ax1 = 0.25f*(PP[r1*2]   + PP[(r1+1)*2]   + PP[(r1+3)*2]   + PP[(r1+4)*2]);
                float ay1 = 0.25f*(PP[r1*2+1] + PP[(r1+1)*2+1] + PP[(r1+3)*2+1] + PP[(r1+4)*2+1]);
                #pragma unroll
                for (int nf = 0; nf < 4; nf++) {
                    int n = wn*32 + nf*8 + qc;
                    float b0 = B[n],   w0x = PW[n],   w0y = PW[128+n],   w0ax = PW[256+n],   w0ay = PW[384+n];
                    float b1 = B[n+1], w1x = PW[n+1], w1y = PW[128+n+1], w1ax = PW[256+n+1], w1ay = PW[384+n+1];
                    float v00 = acc1[mf][nf][0] + b0 + px0*w0x + py0*w0y + ax0*w0ax + ay0*w0ay;
                    float v01 = acc1[mf][nf][1] + b1 + px0*w1x + py0*w1y + ax0*w1ax + ay0*w1ay;
                    float v10 = acc1[mf][nf][2] + b0 + px1*w0x + py1*w0y + ax1*w0ax + ay1*w0ay;
                    float v11 = acc1[mf][nf][3] + b1 + px1*w1x + py1*w1y + ax1*w1ax + ay1*w1ay;
                    __nv_bfloat162 h0 = __float22bfloat162_rn(make_float2(fmaxf(v00,0.f), fmaxf(v01,0.f)));
                    __nv_bfloat162 h1 = __float22bfloat162_rn(make_float2(fmaxf(v10,0.f), fmaxf(v11,0.f)));
                    *(uint32_t*)(sm + SM_HS + hr*LDW + n*2) = *(uint32_t*)&h0;
                    *(uint32_t*)(sm + SM_HS + r1*LDW + n*2) = *(uint32_t*)&h1;
                }
            }
            // halo n8 sub-block: rows 128..131 (rlo<4), cols wn*32 + wm*8 + qc
            if (rlo < 4) {
                int hr = 128 + rlo;
                float px0 = PP[(hr+2)*2],  py0 = PP[(hr+2)*2+1];
                float ax0 = 0.25f*(PP[hr*2]   + PP[(hr+1)*2]   + PP[(hr+3)*2]   + PP[(hr+4)*2]);
                float ay0 = 0.25f*(PP[hr*2+1] + PP[(hr+1)*2+1] + PP[(hr+3)*2+1] + PP[(hr+4)*2+1]);
                int n = wn*32 + wm*8 + qc;
                float b0 = B[n],   w0x = PW[n],   w0y = PW[128+n],   w0ax = PW[256+n],   w0ay = PW[384+n];
                float b1 = B[n+1], w1x = PW[n+1], w1y = PW[128+n+1], w1ax = PW[256+n+1], w1ay = PW[384+n+1];
                float v00 = accH[0] + b0 + px0*w0x + py0*w0y + ax0*w0ax + ay0*w0ay;
                float v01 = accH[1] + b1 + px0*w1x + py0*w1y + ax0*w1ax + ay0*w1ay;
                __nv_bfloat162 h0 = __float22bfloat162_rn(make_float2(fmaxf(v00,0.f), fmaxf(v01,0.f)));
                *(uint32_t*)(sm + SM_HS + hr*LDW + n*2) = *(uint32_t*)&h0;
            }
        }
        __syncthreads();   // HS complete; XR now dead

        // ---- prefetch-gather next tile's features into XR ----
        if (t + 1 < TILES_PER_CTA) {
            int r0n = ((t+1)*GRID_C + blockIdx.x) * 128;
            int n0n = r0n & (NV-1);
            gather_tile(feature, poly_in, sm, r0n - n0n, n0n, step, tid);
        }

        // ---- Hn ring stencil (rows 0..127), bf16x2 SIMD ----
        for (int w = tid; w < 128*32; w += 512) {
            int r = w >> 5, j = w & 31;
            uint2 a = *(uint2*)(sm + SM_HS + (r  )*LDW + j*8);
            uint2 b = *(uint2*)(sm + SM_HS + (r+1)*LDW + j*8);
            uint2 c = *(uint2*)(sm + SM_HS + (r+3)*LDW + j*8);
            uint2 d = *(uint2*)(sm + SM_HS + (r+4)*LDW + j*8);
            *(uint2*)(sm + SM_HN + r*LDW + j*8) = ring4_bf16x4(a, b, c, d);
        }
        __syncthreads();

        // ---- MMA2: merged single loop (self + neighbor interleaved) ----
        float acc2[2][4][4];
        #pragma unroll
        for (int mf = 0; mf < 2; mf++)
            #pragma unroll
            for (int nf = 0; nf < 4; nf++)
                #pragma unroll
                for (int j = 0; j < 4; j++) acc2[mf][nf][j] = 0.f;

        #pragma unroll
        for (int kt = 0; kt < 8; kt++) {
            uint32_t as[2][4], an[2][4];
            #pragma unroll
            for (int mf = 0; mf < 2; mf++) {
                ldmx4(as[mf], sb + SM_HS + (2 + wm*32 + mf*16 + l7 + l8*8)*LDW + l16*16 + kt*32);
                ldmx4(an[mf], sb + SM_HN + (    wm*32 + mf*16 + l7 + l8*8)*LDW + l16*16 + kt*32);
            }
            #pragma unroll
            for (int nf2 = 0; nf2 < 2; nf2++) {
                uint32_t bs[4], bn[4];
                ldmx4(bs, sb + SM_W2S + (wn*32 + nf2*16 + l16*8 + l7)*LDW + kt*32 + l8*16);
                ldmx4(bn, sb + SM_W2N + (wn*32 + nf2*16 + l16*8 + l7)*LDW + kt*32 + l8*16);
                #pragma unroll
                for (int mf = 0; mf < 2; mf++) {
                    mma16816(acc2[mf][2*nf2],   as[mf], bs[0], bs[1]);
                    mma16816(acc2[mf][2*nf2+1], as[mf], bs[2], bs[3]);
                    mma16816(acc2[mf][2*nf2],   an[mf], bn[0], bn[1]);
                    mma16816(acc2[mf][2*nf2+1], an[mf], bn[2], bn[3]);
                }
            }
        }

        // ---- relu + FC(128->2) + poly update ----
        {
            const float* B  = (const float*)(sm + SM_B2);
            const float* FC = (const float*)(sm + SM_FC);
            int rlo = lane >> 2, qc = (lane & 3)*2;
            float pr[2][2][2];
            #pragma unroll
            for (int mf = 0; mf < 2; mf++)
                #pragma unroll
                for (int rh = 0; rh < 2; rh++) { pr[mf][rh][0] = 0.f; pr[mf][rh][1] = 0.f; }
            #pragma unroll
            for (int mf = 0; mf < 2; mf++)
                #pragma unroll
                for (int nf = 0; nf < 4; nf++) {
                    int n = wn*32 + nf*8 + qc;
                    float b0 = B[n], b1 = B[n+1];
                    float h00 = fmaxf(acc2[mf][nf][0] + b0, 0.f);
                    float h01 = fmaxf(acc2[mf][nf][1] + b1, 0.f);
                    float h10 = fmaxf(acc2[mf][nf][2] + b0, 0.f);
                    float h11 = fmaxf(acc2[mf][nf][3] + b1, 0.f);
                    float f0x = FC[n*2], f0y = FC[n*2+1], f1x = FC[(n+1)*2], f1y = FC[(n+1)*2+1];
                    pr[mf][0][0] += h00*f0x + h01*f1x;  pr[mf][0][1] += h00*f0y + h01*f1y;
                    pr[mf][1][0] += h10*f0x + h11*f1x;  pr[mf][1][1] += h10*f0y + h11*f1y;
                }
            #pragma unroll
            for (int mf = 0; mf < 2; mf++)
                #pragma unroll
                for (int rh = 0; rh < 2; rh++)
                    #pragma unroll
                    for (int j = 0; j < 2; j++) {
                        pr[mf][rh][j] += __shfl_xor_sync(0xffffffffu, pr[mf][rh][j], 1);
                        pr[mf][rh][j] += __shfl_xor_sync(0xffffffffu, pr[mf][rh][j], 2);
                    }
            float* RED = (float*)(sm + SM_RED);
            if ((lane & 3) == 0) {
                #pragma unroll
                for (int mf = 0; mf < 2; mf++)
                    #pragma unroll
                    for (int rh = 0; rh < 2; rh++) {
                        int row = wm*32 + mf*16 + rh*8 + rlo;
                        RED[row*8 + wn*2 + 0] = pr[mf][rh][0];
                        RED[row*8 + wn*2 + 1] = pr[mf][rh][1];
                    }
            }
            __syncthreads();
            if (tid < 256) {
                int row = tid >> 1, j = tid & 1;
                float s = RED[row*8 + j] + RED[row*8 + 2 + j]
                        + RED[row*8 + 4 + j] + RED[row*8 + 6 + j] + bfc_g[j];
                poly_out[(size_t)(r0 + row)*2 + j] =
                    ((const float*)(sm + SM_PP))[(row + 4)*2 + j] + s;
            }
        }
    }
}

// ---------------------------------------------------------------------------
extern "C" void kernel_launch(void* const* d_in, const int* in_sizes, int n_in,
                              void* d_out, int out_size)
{
    const float* feature    = (const float*)d_in[0];
    const float* init_polys = (const float*)d_in[1];
    /* d_in[2] = adj (fixed ring graph -> stencil) */
    const float* W1s = (const float*)d_in[3];
    const float* W1n = (const float*)d_in[4];
    const float* b1  = (const float*)d_in[5];
    const float* W2s = (const float*)d_in[6];
    const float* W2n = (const float*)d_in[7];
    const float* b2  = (const float*)d_in[8];
    const float* Wfc = (const float*)d_in[9];
    const float* bfc = (const float*)d_in[10];

    cudaFuncSetAttribute(gemm12_kernel, cudaFuncAttributeMaxDynamicSharedMemorySize, SM_TOTAL);

    float *polyA, *polyB;
    cudaGetSymbolAddress((void**)&polyA, g_polyA);
    cudaGetSymbolAddress((void**)&polyB, g_polyB);

    prep_kernel<<<dim3(3,8), 256>>>(W1s, W1n, W2s, W2n);

    float* pouts[3] = { polyA, polyB, (float*)d_out };
    const float* pin = init_polys;
    for (int i = 0; i < 3; i++) {
        gemm12_kernel<<<GRID_C, 512, SM_TOTAL>>>(feature, pin, pouts[i],
                                                 b1 + i*S, b2 + i*S,
                                                 Wfc + i*S*2, bfc + i*2, i);
        pin = pouts[i];
    }
}

// round 15
// speedup vs baseline: 1.5631x; 1.5631x over previous
#include <cuda_runtime.h>
#include <cuda_bf16.h>
#include <cstdint>

#define GRID_W 112
#define HW (GRID_W*GRID_W)
#define NV 512
#define NP 128
#define M (NP*NV)        /* 65536 rows */
#define S 128
#define GRID_C 128       /* persistent CTAs */
#define TILES_PER_CTA 4

// ---------------------------------------------------------------------------
// PTX helpers (sm_80+ : valid for compute_103)
// ---------------------------------------------------------------------------
__device__ __forceinline__ uint32_t smem_u32(const void* p) {
    uint32_t a;
    asm("{ .reg .u64 t; cvta.to.shared.u64 t, %1; cvt.u32.u64 %0, t; }" : "=r"(a) : "l"(p));
    return a;
}
__device__ __forceinline__ void ldmx4(uint32_t* r, uint32_t addr) {
    asm volatile("ldmatrix.sync.aligned.m8n8.x4.shared.b16 {%0,%1,%2,%3}, [%4];"
        : "=r"(r[0]), "=r"(r[1]), "=r"(r[2]), "=r"(r[3]) : "r"(addr));
}
__device__ __forceinline__ void mma16816(float* d, const uint32_t* a,
                                         uint32_t b0, uint32_t b1) {
    asm volatile(
        "mma.sync.aligned.m16n8k16.row.col.f32.bf16.bf16.f32 "
        "{%0,%1,%2,%3}, {%4,%5,%6,%7}, {%8,%9}, {%0,%1,%2,%3};"
        : "+f"(d[0]), "+f"(d[1]), "+f"(d[2]), "+f"(d[3])
        : "r"(a[0]), "r"(a[1]), "r"(a[2]), "r"(a[3]), "r"(b0), "r"(b1));
}
#define CP_ASYNC16(dst, src) \
    asm volatile("cp.async.cg.shared.global [%0], [%1], 16;" :: "r"(dst), "l"(src))
#define CP_COMMIT() asm volatile("cp.async.commit_group;")
#define CP_WAIT0()  asm volatile("cp.async.wait_group 0;")

// 4-tap ring average on 4 bf16 lanes (one uint2) : 0.25*((a+b)+(c+d))
__device__ __forceinline__ uint2 ring4_bf16x4(uint2 a, uint2 b, uint2 c, uint2 d) {
    const __nv_bfloat162 q = __float2bfloat162_rn(0.25f);
    __nv_bfloat162 s0 = __hmul2(q, __hadd2(__hadd2(*(__nv_bfloat162*)&a.x, *(__nv_bfloat162*)&b.x),
                                           __hadd2(*(__nv_bfloat162*)&c.x, *(__nv_bfloat162*)&d.x)));
    __nv_bfloat162 s1 = __hmul2(q, __hadd2(__hadd2(*(__nv_bfloat162*)&a.y, *(__nv_bfloat162*)&b.y),
                                           __hadd2(*(__nv_bfloat162*)&c.y, *(__nv_bfloat162*)&d.y)));
    return make_uint2(*(uint32_t*)&s0, *(uint32_t*)&s1);
}

// ---------------------------------------------------------------------------
// Scratch globals
// ---------------------------------------------------------------------------
__device__ __align__(16) __nv_bfloat16 g_featb[(size_t)M*64];   // sampled features
__device__ float g_polyA[(size_t)M*2];
__device__ float g_polyB[(size_t)M*2];
__device__ __align__(16) __nv_bfloat16 g_w1T[3*128*128];   // [step][n][k] k<64:W1s, k>=64:W1n
__device__ __align__(16) __nv_bfloat16 g_w2sT[3*128*128];
__device__ __align__(16) __nv_bfloat16 g_w2nT[3*128*128];
__device__ float g_pw[3*4*128];  // poly-weight rows: Ws[64],Ws[65],Wn[64],Wn[65]

// ---------------------------------------------------------------------------
// Combined step-0 sampler (nearest) + weight prep.
// blocks [0,2048): sample; blocks [2048,2072): prep (3 steps x 8 slices).
// ---------------------------------------------------------------------------
__global__ void sample0_prep_kernel(const float* __restrict__ feature,
                                    const float* __restrict__ poly,
                                    const float* __restrict__ W1s,
                                    const float* __restrict__ W1n,
                                    const float* __restrict__ W2s,
                                    const float* __restrict__ W2n)
{
    if (blockIdx.x < 2048) {
        int t = threadIdx.x;
        int c4 = t & 7, vy = t >> 3;
        int v = blockIdx.x * 32 + vy;
        int p = v >> 9;
        float px = poly[v*2+0];
        float py = poly[v*2+1];
        const float4* fb = (const float4*)(feature + (size_t)p * HW * 64);
        int xi = (int)fminf(fmaxf(floorf(px*GRID_W), 0.f), 111.f);
        int yi = (int)fminf(fmaxf(floorf(py*GRID_W), 0.f), 111.f);
        size_t base = (size_t)(xi + yi*GRID_W)*16;
        #pragma unroll
        for (int h = 0; h < 2; h++) {
            float4 val = fb[base + c4 + h*8];
            __nv_bfloat162 o0 = __float22bfloat162_rn(make_float2(val.x, val.y));
            __nv_bfloat162 o1 = __float22bfloat162_rn(make_float2(val.z, val.w));
            *(uint2*)(g_featb + (size_t)v*64 + (c4 + h*8)*4) =
                make_uint2(*(uint32_t*)&o0, *(uint32_t*)&o1);
        }
        return;
    }
    int b = blockIdx.x - 2048;
    int i = b >> 3;
    int slice = b & 7;
    int tid = threadIdx.x + slice*256;          // 0..2047 across slices
    const float* w1s = W1s + (size_t)i*66*128;
    const float* w1n = W1n + (size_t)i*66*128;
    for (int idx = tid; idx < 128*128; idx += 2048) {
        int n = idx >> 7, k = idx & 127;
        float v = (k < 64) ? w1s[k*128 + n] : w1n[(k-64)*128 + n];
        g_w1T[(size_t)i*16384 + idx] = __float2bfloat16(v);
    }
    if (slice == 0 && threadIdx.x < 128) {
        int t = threadIdx.x;
        g_pw[i*512 +       t] = w1s[64*128 + t];
        g_pw[i*512 + 128 + t] = w1s[65*128 + t];
        g_pw[i*512 + 256 + t] = w1n[64*128 + t];
        g_pw[i*512 + 384 + t] = w1n[65*128 + t];
    }
    const float* w2s = W2s + (size_t)i*128*128;
    const float* w2n = W2n + (size_t)i*128*128;
    for (int idx = tid; idx < 128*128; idx += 2048) {
        int n = idx >> 7, k = idx & 127;
        g_w2sT[(size_t)i*16384 + idx] = __float2bfloat16(w2s[k*128 + n]);
        g_w2nT[(size_t)i*16384 + idx] = __float2bfloat16(w2n[k*128 + n]);
    }
}

// ---------------------------------------------------------------------------
// Sampler (steps 1,2: bilinear): gather -> g_featb [M,64] bf16
// block (8,32): tx = chunk (handles c4 = tx and tx+8), ty = vertex.
// ---------------------------------------------------------------------------
__global__ void sample_kernel(const float* __restrict__ feature,
                              const float* __restrict__ poly)
{
    int v  = blockIdx.x * 32 + threadIdx.y;
    int c4 = threadIdx.x;               // 0..7; chunks c4 and c4+8
    int p  = v >> 9;
    float px = poly[v*2+0];
    float py = poly[v*2+1];
    const float4* fb = (const float4*)(feature + (size_t)p * HW * 64);
    float Xs = px*GRID_W, Ys = py*GRID_W;
    float X0 = floorf(Xs), Y0 = floorf(Ys);
    float wx = Xs - X0, wy = Ys - Y0;
    int x0 = (int)fminf(fmaxf(X0,     0.f), 111.f);
    int x1 = (int)fminf(fmaxf(X0+1.f, 0.f), 111.f);
    int y0 = (int)fminf(fmaxf(Y0,     0.f), 111.f);
    int y1 = (int)fminf(fmaxf(Y0+1.f, 0.f), 111.f);
    size_t b00 = (size_t)(x0 + y0*GRID_W)*16;
    size_t b01 = (size_t)(x0 + y1*GRID_W)*16;
    size_t b10 = (size_t)(x1 + y0*GRID_W)*16;
    size_t b11 = (size_t)(x1 + y1*GRID_W)*16;
    float4 m00[2], m01[2], m10[2], m11[2];
    #pragma unroll
    for (int h = 0; h < 2; h++) {
        int cc = c4 + h*8;
        m00[h] = fb[b00 + cc];
        m01[h] = fb[b01 + cc];
        m10[h] = fb[b10 + cc];
        m11[h] = fb[b11 + cc];
    }
    float w00 = (1.f-wx)*(1.f-wy), w01 = (1.f-wx)*wy;
    float w10 = wx*(1.f-wy),       w11 = wx*wy;
    #pragma unroll
    for (int h = 0; h < 2; h++) {
        float4 val;
        val.x = w00*m00[h].x + w01*m01[h].x + w10*m10[h].x + w11*m11[h].x;
        val.y = w00*m00[h].y + w01*m01[h].y + w10*m10[h].y + w11*m11[h].y;
        val.z = w00*m00[h].z + w01*m01[h].z + w10*m10[h].z + w11*m11[h].z;
        val.w = w00*m00[h].w + w01*m01[h].w + w10*m10[h].w + w11*m11[h].w;
        __nv_bfloat162 o0 = __float22bfloat162_rn(make_float2(val.x, val.y));
        __nv_bfloat162 o1 = __float22bfloat162_rn(make_float2(val.z, val.w));
        *(uint2*)(g_featb + (size_t)v*64 + (c4 + h*8)*4) =
            make_uint2(*(uint32_t*)&o0, *(uint32_t*)&o1);
    }
}

// ---------------------------------------------------------------------------
// Persistent fused GEMM kernel. 128 CTAs x 4 tiles, 512 thr, 16 warps (4m x 4n).
// MMA1 halo tile balanced across all warps; sliding-window stencils.
// ---------------------------------------------------------------------------
#define LDW 272
#define LDX 144
#define SM_W1    0
#define SM_W2S   34816
#define SM_W2N   69632
#define SM_HS    104448
#define SM_HN    140352
#define SM_XN    175168
#define SM_XR    195904
#define SM_PW    217216
#define SM_B1    219264
#define SM_B2    219776
#define SM_FC    220288
#define SM_PP    221312   /* 136*2 f32 */
#define SM_RED   222400   /* 128*8 f32 */
#define SM_TOTAL 226496

__global__ void __launch_bounds__(512, 1)
gemm12_kernel(const float* __restrict__ poly_in,
              float* __restrict__ poly_out,
              const float* __restrict__ b1_g,
              const float* __restrict__ b2_g,
              const float* __restrict__ wfc_g,
              const float* __restrict__ bfc_g,
              int step)
{
    extern __shared__ char sm[];
    uint32_t sb = smem_u32(sm);
    int tid = threadIdx.x, wid = tid >> 5, lane = tid & 31;
    int wm = wid & 3, wn = wid >> 2;
    int l7 = lane & 7, l8 = (lane >> 3) & 1, l16 = (lane >> 4) & 1;

    // ------- prologue: cp.async weights + tile0 XR; scalars; XR zero-pad ----
    {
        const char* w1p  = (const char*)(g_w1T  + (size_t)step*16384);
        const char* w2sp = (const char*)(g_w2sT + (size_t)step*16384);
        const char* w2np = (const char*)(g_w2nT + (size_t)step*16384);
        for (int idx = tid; idx < 128*16; idx += 512) {
            int r = idx >> 4, q = idx & 15;
            CP_ASYNC16(sb + SM_W1  + r*LDW + q*16, w1p  + idx*16);
            CP_ASYNC16(sb + SM_W2S + r*LDW + q*16, w2sp + idx*16);
            CP_ASYNC16(sb + SM_W2N + r*LDW + q*16, w2np + idx*16);
        }
        if (tid < 128) {
            ((float*)(sm + SM_B1))[tid] = b1_g[tid];
            ((float*)(sm + SM_B2))[tid] = b2_g[tid];
        }
        if (tid < 256) ((float*)(sm + SM_FC))[tid] = wfc_g[tid];
        ((float*)(sm + SM_PW))[tid] = g_pw[step*512 + tid];
        if (tid < 432) {                      // zero XR rows 136..147 (one-time)
            int r = 136 + tid/36, w = tid%36;
            *(uint32_t*)(sm + SM_XR + r*LDX + w*4) = 0;
        }
        // prefetch tile 0 Xs
        int r0 = blockIdx.x * 128;
        int n0 = r0 & (NV-1);
        int pbase = r0 - n0;
        for (int idx = tid; idx < 136*8; idx += 512) {
            int r = idx >> 3, q = idx & 7;
            int n = (n0 + r - 4 + NV) & (NV-1);
            CP_ASYNC16(sb + SM_XR + r*LDX + q*16,
                       (const char*)g_featb + ((size_t)(pbase + n)*64 + q*8)*2);
        }
        CP_COMMIT();
    }

    for (int t = 0; t < TILES_PER_CTA; t++) {
        int r0 = (t*GRID_C + blockIdx.x) * 128;
        int n0 = r0 & (NV-1);
        int pbase = r0 - n0;

        CP_WAIT0();
        __syncthreads();   // XR(t)+weights ready; prior tile fully done

        // poly rows -4..131 for this tile
        if (tid < 272) {
            int rr = tid >> 1, c = tid & 1;
            int g = pbase + ((n0 + rr - 4 + NV) & (NV-1));
            ((float*)(sm + SM_PP))[tid] = poly_in[(size_t)g*2 + c];
        }

        // ---- XN ring stencil (rows 0..143), sliding window ----
        // 16 uint2-cols x 24 strips of 6 rows = 384 threads
        if (tid < 384) {
            int j = tid & 15, s = tid >> 4;
            int rb = s*6;
            uint2 w0 = *(uint2*)(sm + SM_XR + (rb  )*LDX + j*8);
            uint2 w1 = *(uint2*)(sm + SM_XR + (rb+1)*LDX + j*8);
            uint2 w2 = *(uint2*)(sm + SM_XR + (rb+2)*LDX + j*8);
            uint2 w3 = *(uint2*)(sm + SM_XR + (rb+3)*LDX + j*8);
            #pragma unroll
            for (int i2 = 0; i2 < 6; i2++) {
                uint2 w4 = *(uint2*)(sm + SM_XR + (rb+4+i2)*LDX + j*8);
                *(uint2*)(sm + SM_XN + (rb+i2)*LDX + j*8) = ring4_bf16x4(w0, w1, w3, w4);
                w0 = w1; w1 = w2; w2 = w3; w3 = w4;
            }
        }
        __syncthreads();   // XN ready (XR stays live through MMA1)

        // ---- MMA1: K=128 (kt<4 self from XR; kt>=4 ring from XN) ----
        //      Halo (rows 128..143): every warp computes one n8 sub-block.
        float acc1[2][4][4];
        float accH[4];
        #pragma unroll
        for (int mf = 0; mf < 2; mf++)
            #pragma unroll
            for (int nf = 0; nf < 4; nf++)
                #pragma unroll
                for (int j = 0; j < 4; j++) acc1[mf][nf][j] = 0.f;
        #pragma unroll
        for (int j = 0; j < 4; j++) accH[j] = 0.f;

        int halo_nf2 = wm >> 1;
        int halo_hi  = wm & 1;

        #pragma unroll
        for (int kt = 0; kt < 8; kt++) {
            uint32_t a[2][4], ah[4];
            #pragma unroll
            for (int mf = 0; mf < 2; mf++) {
                uint32_t arow = wm*32 + mf*16 + l7 + l8*8;
                uint32_t addr = (kt < 4)
                    ? sb + SM_XR + (2 + arow)*LDX + l16*16 + kt*32
                    : sb + SM_XN + arow*LDX + l16*16 + (kt-4)*32;
                ldmx4(a[mf], addr);
            }
            {
                uint32_t hrow = 128 + l7 + l8*8;
                uint32_t addr = (kt < 4)
                    ? sb + SM_XR + (2 + hrow)*LDX + l16*16 + kt*32
                    : sb + SM_XN + hrow*LDX + l16*16 + (kt-4)*32;
                ldmx4(ah, addr);
            }
            #pragma unroll
            for (int nf2 = 0; nf2 < 2; nf2++) {
                uint32_t b[4];
                ldmx4(b, sb + SM_W1 + (wn*32 + nf2*16 + l16*8 + l7)*LDW + kt*32 + l8*16);
                #pragma unroll
                for (int mf = 0; mf < 2; mf++) {
                    mma16816(acc1[mf][2*nf2],   a[mf], b[0], b[1]);
                    mma16816(acc1[mf][2*nf2+1], a[mf], b[2], b[3]);
                }
                if (nf2 == halo_nf2) {
                    if (halo_hi) mma16816(accH, ah, b[2], b[3]);
                    else         mma16816(accH, ah, b[0], b[1]);
                }
            }
        }

        // ---- epilogue1 -> Hs (HS private; no pre-sync needed) ----
        {
            const float* PP = (const float*)(sm + SM_PP);
            const float* B  = (const float*)(sm + SM_B1);
            const float* PW = (const float*)(sm + SM_PW);
            int rlo = lane >> 2, qc = (lane & 3)*2;
            #pragma unroll
            for (int mf = 0; mf < 2; mf++) {
                int hr = wm*32 + mf*16 + rlo;
                float px0 = PP[(hr+2)*2],  py0 = PP[(hr+2)*2+1];
                float ax0 = 0.25f*(PP[hr*2]   + PP[(hr+1)*2]   + PP[(hr+3)*2]   + PP[(hr+4)*2]);
                float ay0 = 0.25f*(PP[hr*2+1] + PP[(hr+1)*2+1] + PP[(hr+3)*2+1] + PP[(hr+4)*2+1]);
                int r1 = hr + 8;
                float px1 = PP[(r1+2)*2],  py1 = PP[(r1+2)*2+1];
                float ax1 = 0.25f*(PP[r1*2]   + PP[(r1+1)*2]   + PP[(r1+3)*2]   + PP[(r1+4)*2]);
                float ay1 = 0.25f*(PP[r1*2+1] + PP[(r1+1)*2+1] + PP[(r1+3)*2+1] + PP[(r1+4)*2+1]);
                #pragma unroll
                for (int nf = 0; nf < 4; nf++) {
                    int n = wn*32 + nf*8 + qc;
                    float b0 = B[n],   w0x = PW[n],   w0y = PW[128+n],   w0ax = PW[256+n],   w0ay = PW[384+n];
                    float b1 = B[n+1], w1x = PW[n+1], w1y = PW[128+n+1], w1ax = PW[256+n+1], w1ay = PW[384+n+1];
                    float v00 = acc1[mf][nf][0] + b0 + px0*w0x + py0*w0y + ax0*w0ax + ay0*w0ay;
                    float v01 = acc1[mf][nf][1] + b1 + px0*w1x + py0*w1y + ax0*w1ax + ay0*w1ay;
                    float v10 = acc1[mf][nf][2] + b0 + px1*w0x + py1*w0y + ax1*w0ax + ay1*w0ay;
                    float v11 = acc1[mf][nf][3] + b1 + px1*w1x + py1*w1y + ax1*w1ax + ay1*w1ay;
                    __nv_bfloat162 h0 = __float22bfloat162_rn(make_float2(fmaxf(v00,0.f), fmaxf(v01,0.f)));
                    __nv_bfloat162 h1 = __float22bfloat162_rn(make_float2(fmaxf(v10,0.f), fmaxf(v11,0.f)));
                    *(uint32_t*)(sm + SM_HS + hr*LDW + n*2) = *(uint32_t*)&h0;
                    *(uint32_t*)(sm + SM_HS + r1*LDW + n*2) = *(uint32_t*)&h1;
                }
            }
            // halo n8 sub-block: rows 128..131 (rlo<4), cols wn*32 + wm*8 + qc
            if (rlo < 4) {
                int hr = 128 + rlo;
                float px0 = PP[(hr+2)*2],  py0 = PP[(hr+2)*2+1];
                float ax0 = 0.25f*(PP[hr*2]   + PP[(hr+1)*2]   + PP[(hr+3)*2]   + PP[(hr+4)*2]);
                float ay0 = 0.25f*(PP[hr*2+1] + PP[(hr+1)*2+1] + PP[(hr+3)*2+1] + PP[(hr+4)*2+1]);
                int n = wn*32 + wm*8 + qc;
                float b0 = B[n],   w0x = PW[n],   w0y = PW[128+n],   w0ax = PW[256+n],   w0ay = PW[384+n];
                float b1 = B[n+1], w1x = PW[n+1], w1y = PW[128+n+1], w1ax = PW[256+n+1], w1ay = PW[384+n+1];
                float v00 = accH[0] + b0 + px0*w0x + py0*w0y + ax0*w0ax + ay0*w0ay;
                float v01 = accH[1] + b1 + px0*w1x + py0*w1y + ax0*w1ax + ay0*w1ay;
                __nv_bfloat162 h0 = __float22bfloat162_rn(make_float2(fmaxf(v00,0.f), fmaxf(v01,0.f)));
                *(uint32_t*)(sm + SM_HS + hr*LDW + n*2) = *(uint32_t*)&h0;
            }
        }
        __syncthreads();   // HS complete; XR now dead

        // ---- prefetch next tile's Xs into XR (overlaps Hn/MMA2/epi2) ----
        if (t + 1 < TILES_PER_CTA) {
            int r0n = ((t+1)*GRID_C + blockIdx.x) * 128;
            int n0n = r0n & (NV-1);
            int pbn = r0n - n0n;
            for (int idx = tid; idx < 136*8; idx += 512) {
                int r = idx >> 3, q = idx & 7;
                int n = (n0n + r - 4 + NV) & (NV-1);
                CP_ASYNC16(sb + SM_XR + r*LDX + q*16,
                           (const char*)g_featb + ((size_t)(pbn + n)*64 + q*8)*2);
            }
            CP_COMMIT();
        }

        // ---- Hn ring stencil (rows 0..127), sliding window ----
        // 32 uint2-cols x 16 strips of 8 rows = 512 threads
        {
            int j = tid & 31, s = tid >> 5;
            int rb = s*8;
            uint2 w0 = *(uint2*)(sm + SM_HS + (rb  )*LDW + j*8);
            uint2 w1 = *(uint2*)(sm + SM_HS + (rb+1)*LDW + j*8);
            uint2 w2 = *(uint2*)(sm + SM_HS + (rb+2)*LDW + j*8);
            uint2 w3 = *(uint2*)(sm + SM_HS + (rb+3)*LDW + j*8);
            #pragma unroll
            for (int i2 = 0; i2 < 8; i2++) {
                uint2 w4 = *(uint2*)(sm + SM_HS + (rb+4+i2)*LDW + j*8);
                *(uint2*)(sm + SM_HN + (rb+i2)*LDW + j*8) = ring4_bf16x4(w0, w1, w3, w4);
                w0 = w1; w1 = w2; w2 = w3; w3 = w4;
            }
        }
        __syncthreads();

        // ---- MMA2: merged single loop (self + neighbor interleaved) ----
        float acc2[2][4][4];
        #pragma unroll
        for (int mf = 0; mf < 2; mf++)
            #pragma unroll
            for (int nf = 0; nf < 4; nf++)
                #pragma unroll
                for (int j = 0; j < 4; j++) acc2[mf][nf][j] = 0.f;

        #pragma unroll
        for (int kt = 0; kt < 8; kt++) {
            uint32_t as[2][4], an[2][4];
            #pragma unroll
            for (int mf = 0; mf < 2; mf++) {
                ldmx4(as[mf], sb + SM_HS + (2 + wm*32 + mf*16 + l7 + l8*8)*LDW + l16*16 + kt*32);
                ldmx4(an[mf], sb + SM_HN + (    wm*32 + mf*16 + l7 + l8*8)*LDW + l16*16 + kt*32);
            }
            #pragma unroll
            for (int nf2 = 0; nf2 < 2; nf2++) {
                uint32_t bs[4], bn[4];
                ldmx4(bs, sb + SM_W2S + (wn*32 + nf2*16 + l16*8 + l7)*LDW + kt*32 + l8*16);
                ldmx4(bn, sb + SM_W2N + (wn*32 + nf2*16 + l16*8 + l7)*LDW + kt*32 + l8*16);
                #pragma unroll
                for (int mf = 0; mf < 2; mf++) {
                    mma16816(acc2[mf][2*nf2],   as[mf], bs[0], bs[1]);
                    mma16816(acc2[mf][2*nf2+1], as[mf], bs[2], bs[3]);
                    mma16816(acc2[mf][2*nf2],   an[mf], bn[0], bn[1]);
                    mma16816(acc2[mf][2*nf2+1], an[mf], bn[2], bn[3]);
                }
            }
        }

        // ---- relu + FC(128->2) + poly update ----
        {
            const float* B  = (const float*)(sm + SM_B2);
            const float* FC = (const float*)(sm + SM_FC);
            int rlo = lane >> 2, qc = (lane & 3)*2;
            float pr[2][2][2];
            #pragma unroll
            for (int mf = 0; mf < 2; mf++)
                #pragma unroll
                for (int rh = 0; rh < 2; rh++) { pr[mf][rh][0] = 0.f; pr[mf][rh][1] = 0.f; }
            #pragma unroll
            for (int mf = 0; mf < 2; mf++)
                #pragma unroll
                for (int nf = 0; nf < 4; nf++) {
                    int n = wn*32 + nf*8 + qc;
                    float b0 = B[n], b1 = B[n+1];
                    float h00 = fmaxf(acc2[mf][nf][0] + b0, 0.f);
                    float h01 = fmaxf(acc2[mf][nf][1] + b1, 0.f);
                    float h10 = fmaxf(acc2[mf][nf][2] + b0, 0.f);
                    float h11 = fmaxf(acc2[mf][nf][3] + b1, 0.f);
                    float f0x = FC[n*2], f0y = FC[n*2+1], f1x = FC[(n+1)*2], f1y = FC[(n+1)*2+1];
                    pr[mf][0][0] += h00*f0x + h01*f1x;  pr[mf][0][1] += h00*f0y + h01*f1y;
                    pr[mf][1][0] += h10*f0x + h11*f1x;  pr[mf][1][1] += h10*f0y + h11*f1y;
                }
            #pragma unroll
            for (int mf = 0; mf < 2; mf++)
                #pragma unroll
                for (int rh = 0; rh < 2; rh++)
                    #pragma unroll
                    for (int j = 0; j < 2; j++) {
                        pr[mf][rh][j] += __shfl_xor_sync(0xffffffffu, pr[mf][rh][j], 1);
                        pr[mf][rh][j] += __shfl_xor_sync(0xffffffffu, pr[mf][rh][j], 2);
                    }
            float* RED = (float*)(sm + SM_RED);
            if ((lane & 3) == 0) {
                #pragma unroll
                for (int mf = 0; mf < 2; mf++)
                    #pragma unroll
                    for (int rh = 0; rh < 2; rh++) {
                        int row = wm*32 + mf*16 + rh*8 + rlo;
                        RED[row*8 + wn*2 + 0] = pr[mf][rh][0];
                        RED[row*8 + wn*2 + 1] = pr[mf][rh][1];
                    }
            }
            __syncthreads();
            if (tid < 256) {
                int row = tid >> 1, j = tid & 1;
                float s = RED[row*8 + j] + RED[row*8 + 2 + j]
                        + RED[row*8 + 4 + j] + RED[row*8 + 6 + j] + bfc_g[j];
                poly_out[(size_t)(r0 + row)*2 + j] =
                    ((const float*)(sm + SM_PP))[(row + 4)*2 + j] + s;
            }
        }
    }
}

// ---------------------------------------------------------------------------
extern "C" void kernel_launch(void* const* d_in, const int* in_sizes, int n_in,
                              void* d_out, int out_size)
{
    const float* feature    = (const float*)d_in[0];
    const float* init_polys = (const float*)d_in[1];
    /* d_in[2] = adj (fixed ring graph -> stencil) */
    const float* W1s = (const float*)d_in[3];
    const float* W1n = (const float*)d_in[4];
    const float* b1  = (const float*)d_in[5];
    const float* W2s = (const float*)d_in[6];
    const float* W2n = (const float*)d_in[7];
    const float* b2  = (const float*)d_in[8];
    const float* Wfc = (const float*)d_in[9];
    const float* bfc = (const float*)d_in[10];

    cudaFuncSetAttribute(gemm12_kernel, cudaFuncAttributeMaxDynamicSharedMemorySize, SM_TOTAL);

    float *polyA, *polyB;
    cudaGetSymbolAddress((void**)&polyA, g_polyA);
    cudaGetSymbolAddress((void**)&polyB, g_polyB);

    // fused step-0 sampler + weight prep (independent work, one launch)
    sample0_prep_kernel<<<2072, 256>>>(feature, init_polys, W1s, W1n, W2s, W2n);

    float* pouts[3] = { polyA, polyB, (float*)d_out };
    const float* pin = init_polys;
    for (int i = 0; i < 3; i++) {
        if (i > 0) sample_kernel<<<M/32, dim3(8,32)>>>(feature, pin);
        gemm12_kernel<<<GRID_C, 512, SM_TOTAL>>>(pin, pouts[i],
                                                 b1 + i*S, b2 + i*S,
                                                 Wfc + i*S*2, bfc + i*2, i);
        pin = pouts[i];
    }
}